// round 10
// baseline (speedup 1.0000x reference)
#include <cuda_runtime.h>
#include <cuda_fp16.h>
#include <cstdint>

#define KK 4096
#define NN 11008
#define MM 4096

// scratch
__device__ __half g_A[(size_t)MM * KK];   // x in fp16, [M, K]
__device__ __half g_W[(size_t)KK * NN];   // dequantized W in fp16, [K, N]

// ---------------------------------------------------------------------------
// helpers
// ---------------------------------------------------------------------------
__device__ __forceinline__ uint32_t smem_u32(const void* p) {
    uint32_t a;
    asm("{ .reg .u64 t; cvta.to.shared.u64 t, %1; cvt.u32.u64 %0, t; }"
        : "=r"(a) : "l"(p));
    return a;
}
__device__ __forceinline__ void cp16(uint32_t s, const void* g) {
    asm volatile("cp.async.cg.shared.global [%0], [%1], 16;" :: "r"(s), "l"(g));
}
__device__ __forceinline__ void ldsm4(uint32_t& r0, uint32_t& r1, uint32_t& r2,
                                      uint32_t& r3, uint32_t a) {
    asm volatile("ldmatrix.sync.aligned.m8n8.x4.shared.b16 {%0,%1,%2,%3}, [%4];"
                 : "=r"(r0), "=r"(r1), "=r"(r2), "=r"(r3) : "r"(a));
}
__device__ __forceinline__ void ldsm4t(uint32_t& r0, uint32_t& r1, uint32_t& r2,
                                       uint32_t& r3, uint32_t a) {
    asm volatile("ldmatrix.sync.aligned.m8n8.x4.trans.shared.b16 {%0,%1,%2,%3}, [%4];"
                 : "=r"(r0), "=r"(r1), "=r"(r2), "=r"(r3) : "r"(a));
}
__device__ __forceinline__ void mma16816(float* d, const uint32_t* a,
                                         uint32_t b0, uint32_t b1) {
    asm volatile("mma.sync.aligned.m16n8k16.row.col.f32.f16.f16.f32 "
                 "{%0,%1,%2,%3}, {%4,%5,%6,%7}, {%8,%9}, {%0,%1,%2,%3};"
                 : "+f"(d[0]), "+f"(d[1]), "+f"(d[2]), "+f"(d[3])
                 : "r"(a[0]), "r"(a[1]), "r"(a[2]), "r"(a[3]), "r"(b0), "r"(b1));
}

// ---------------------------------------------------------------------------
// 1) x fp32 -> fp16
// ---------------------------------------------------------------------------
__global__ void convert_x_kernel(const float* __restrict__ x) {
    size_t i = ((size_t)blockIdx.x * blockDim.x + threadIdx.x) * 4;
    float4 v = *reinterpret_cast<const float4*>(x + i);
    __half2* p = reinterpret_cast<__half2*>(g_A + i);
    p[0] = __floats2half2_rn(v.x, v.y);
    p[1] = __floats2half2_rn(v.z, v.w);
}

// ---------------------------------------------------------------------------
// 2) dequant int4 -> fp16 W [K, N]
// ---------------------------------------------------------------------------
__global__ void dequant_kernel(const int* __restrict__ qw,
                               const int* __restrict__ qz,
                               const float* __restrict__ sc) {
    int idx = blockIdx.x * blockDim.x + threadIdx.x;   // 4096 * 1376 threads
    int k  = idx / (NN / 8);
    int n8 = idx - k * (NN / 8);
    int n0 = n8 * 8;
    int g  = k >> 7;
    unsigned zw = (unsigned)qz[g * (NN / 8) + n8];
    int shift = (k & 7) * 4;
    const int*   qrow = qw + (size_t)(k >> 3) * NN + n0;
    const float* srow = sc + (size_t)g * NN + n0;
    union { __half h[8]; uint4 v; } r;
#pragma unroll
    for (int j = 0; j < 8; j++) {
        int q = ((unsigned)qrow[j] >> shift) & 0xF;
        int z = (int)((zw >> (4 * j)) & 0xFu) + 1;
        r.h[j] = __float2half_rn((float)(q - z) * srow[j]);
    }
    *reinterpret_cast<uint4*>(g_W + (size_t)k * NN + n0) = r.v;
}

// ---------------------------------------------------------------------------
// 3) HMMA GEMM: out[M,N] = A[M,K] * W[K,N] + bias
//    BM=128 BN=128 BK=64, 3-stage cp.async, 96KB -> 2 CTAs/SM,
//    8 warps as 2m x 4n (warp 64x32), rolling a/b fragment pipeline (no spill)
// ---------------------------------------------------------------------------
#define BM 128
#define BN 128
#define BK 64
#define STAGES 3
#define A_BYTES (BM * BK * 2)              // 16 KB, 128 rows x 128B
#define B_BYTES (BK * BN * 2)              // 16 KB, 64 rows x 256B
#define STAGE_BYTES (A_BYTES + B_BYTES)    // 32 KB
#define SMEM_BYTES (STAGES * STAGE_BYTES)  // 96 KB -> 2 CTAs/SM
#define KITERS (KK / BK)                   // 64

#define SWZA(r, c) ((uint32_t)((r) * 128 + ((((c) ^ ((r) & 7))) << 4)))
#define SWZB(r, c) ((uint32_t)((r) * 256 + ((((c) ^ ((r) & 7))) << 4)))

__global__ void __launch_bounds__(256, 2)
gemm_kernel(const float* __restrict__ bias, float* __restrict__ out) {
    extern __shared__ char smem[];
    const uint32_t sb = smem_u32(smem);
    const int tid = threadIdx.x;
    const int wid = tid >> 5;
    const int lane = tid & 31;
    const int m0 = blockIdx.x * BM;        // 32 m-tiles (fast: share W in L2)
    const int n0 = blockIdx.y * BN;        // 86 n-tiles
    const int wm = wid & 1;                // 0..1 (64 rows)
    const int wn = wid >> 1;               // 0..3 (32 cols)

    // rolling global load pointers (advance by one chunk per load_stage)
    const char* aLoad = (const char*)(g_A + (size_t)m0 * KK);
    const char* bLoad = (const char*)(g_W + n0);

    auto load_stage = [&](int s) {
        uint32_t sA = sb + s * STAGE_BYTES;
        uint32_t sB = sA + A_BYTES;
#pragma unroll
        for (int j = 0; j < 4; j++) {      // A: 1024 x 16B (128 rows x 128B)
            int q = j * 256 + tid;
            int r = q >> 3, c = q & 7;
            cp16(sA + SWZA(r, c), aLoad + (size_t)r * (KK * 2) + c * 16);
        }
#pragma unroll
        for (int j = 0; j < 4; j++) {      // B: 1024 x 16B (64 rows x 256B)
            int q = j * 256 + tid;
            int r = q >> 4, c = q & 15;
            cp16(sB + SWZB(r, c), bLoad + (size_t)r * (NN * 2) + c * 16);
        }
        aLoad += BK * 2;                   // next chunk
        bLoad += (size_t)BK * NN * 2;
    };

    // ---- algebraically reduced LDSM addresses ----
    // A: addr(mi,ks) = aBase[mi] + 32*(ks ^ xk);  B: addr(nb,ks) = ks*4096 + bBase[nb]
    const int x  = lane & 7;
    const int h  = lane >> 4;              // 0/1
    const int xk = x >> 1;                 // 0..3
    const int xb = (x & 1) ^ h;
    uint32_t aBase[4];
#pragma unroll
    for (int mi = 0; mi < 4; mi++)
        aBase[mi] = (uint32_t)((wm * 64 + mi * 16 + (lane & 15)) * 128 + 16 * xb);
    uint32_t kso[4];
#pragma unroll
    for (int ks = 0; ks < 4; ks++) kso[ks] = (uint32_t)(32 * (ks ^ xk));
    uint32_t bBase[2];
#pragma unroll
    for (int nb = 0; nb < 2; nb++) {
        int c = wn * 4 + nb * 2 + h;
        bBase[nb] = (uint32_t)((lane & 15) * 256 + ((c ^ x) << 4));
    }

    uint32_t af[2][4];                     // a fragment rolling buffer (per mi)
    uint32_t bf[2][8];                     // b fragment double buffer (per ks)

    // prologue: 2 stages in flight
    load_stage(0);
    asm volatile("cp.async.commit_group;" ::: "memory");
    load_stage(1);
    asm volatile("cp.async.commit_group;" ::: "memory");

    float acc[4][4][4];
#pragma unroll
    for (int i = 0; i < 4; i++)
#pragma unroll
        for (int j = 0; j < 4; j++)
#pragma unroll
            for (int e = 0; e < 4; e++) acc[i][j][e] = 0.f;

    int stage = 0;
    for (int it = 0; it < KITERS; it++) {
        asm volatile("cp.async.wait_group 1;" ::: "memory");
        __syncthreads();

        const uint32_t sA = sb + stage * STAGE_BYTES;
        const uint32_t sB = sA + A_BYTES;

        // first fragments of this chunk
        ldsm4t(bf[0][0], bf[0][1], bf[0][2], bf[0][3], sB + bBase[0]);
        ldsm4t(bf[0][4], bf[0][5], bf[0][6], bf[0][7], sB + bBase[1]);
        ldsm4(af[0][0], af[0][1], af[0][2], af[0][3], sA + aBase[0] + kso[0]);

        // refill the stage freed by the previous iteration
        if (it + 2 < KITERS) {
            int ls = stage + 2 >= STAGES ? stage + 2 - STAGES : stage + 2;
            load_stage(ls);
        }
        asm volatile("cp.async.commit_group;" ::: "memory");

#pragma unroll
        for (int ks = 0; ks < 4; ks++) {
#pragma unroll
            for (int mi = 0; mi < 4; mi++) {
                if (mi == 0 && ks < 3) {   // prefetch b(ks+1)
                    int nb = (ks + 1) & 1;
                    ldsm4t(bf[nb][0], bf[nb][1], bf[nb][2], bf[nb][3],
                           sB + (uint32_t)((ks + 1) * 4096) + bBase[0]);
                    ldsm4t(bf[nb][4], bf[nb][5], bf[nb][6], bf[nb][7],
                           sB + (uint32_t)((ks + 1) * 4096) + bBase[1]);
                }
                if (mi < 3) {              // prefetch a(ks, mi+1)
                    int ab = (mi + 1) & 1;
                    ldsm4(af[ab][0], af[ab][1], af[ab][2], af[ab][3],
                          sA + aBase[mi + 1] + kso[ks]);
                } else if (ks < 3) {       // prefetch a(ks+1, 0)
                    ldsm4(af[0][0], af[0][1], af[0][2], af[0][3],
                          sA + aBase[0] + kso[ks + 1]);
                }
                const uint32_t* a = af[mi & 1];
                const uint32_t* b = bf[ks & 1];
                mma16816(acc[mi][0], a, b[0], b[1]);
                mma16816(acc[mi][1], a, b[2], b[3]);
                mma16816(acc[mi][2], a, b[4], b[5]);
                mma16816(acc[mi][3], a, b[6], b[7]);
            }
        }
        stage = stage + 1 >= STAGES ? 0 : stage + 1;
    }

    // epilogue
#pragma unroll
    for (int mi = 0; mi < 4; mi++) {
        int r = m0 + wm * 64 + mi * 16 + (lane >> 2);
#pragma unroll
        for (int ni = 0; ni < 4; ni++) {
            int col = n0 + wn * 32 + ni * 8 + 2 * (lane & 3);
            float b0 = bias[col], b1 = bias[col + 1];
            float2 v0 = make_float2(acc[mi][ni][0] + b0, acc[mi][ni][1] + b1);
            float2 v1 = make_float2(acc[mi][ni][2] + b0, acc[mi][ni][3] + b1);
            *reinterpret_cast<float2*>(out + (size_t)r * NN + col) = v0;
            *reinterpret_cast<float2*>(out + (size_t)(r + 8) * NN + col) = v1;
        }
    }
}

// ---------------------------------------------------------------------------
// launch
// ---------------------------------------------------------------------------
extern "C" void kernel_launch(void* const* d_in, const int* in_sizes, int n_in,
                              void* d_out, int out_size) {
    const float* x    = (const float*)d_in[0];
    const int*   qw   = (const int*)d_in[1];
    const int*   qz   = (const int*)d_in[2];
    const float* sc   = (const float*)d_in[3];
    // d_in[4] = g_idx (k/128 by construction; unused)
    const float* bias = (const float*)d_in[5];
    float* out = (float*)d_out;

    cudaFuncSetAttribute(gemm_kernel, cudaFuncAttributeMaxDynamicSharedMemorySize,
                         SMEM_BYTES);

    convert_x_kernel<<<16384, 256>>>(x);            // 16.78M elems / 4 per thread
    dequant_kernel<<<22016, 256>>>(qw, qz, sc);     // 4096 * 1376 threads
    gemm_kernel<<<dim3(MM / BM, NN / BN), 256, SMEM_BYTES>>>(bias, out);
}

// round 12
// speedup vs baseline: 1.0174x; 1.0174x over previous
#include <cuda_runtime.h>
#include <cuda_fp16.h>
#include <cstdint>

#define KK 4096
#define NN 11008
#define MM 4096

// scratch
__device__ __half g_A[(size_t)MM * KK];   // x in fp16, [M, K]
__device__ __half g_W[(size_t)KK * NN];   // dequantized W in fp16, [K, N]

// ---------------------------------------------------------------------------
// helpers
// ---------------------------------------------------------------------------
__device__ __forceinline__ uint32_t smem_u32(const void* p) {
    uint32_t a;
    asm("{ .reg .u64 t; cvta.to.shared.u64 t, %1; cvt.u32.u64 %0, t; }"
        : "=r"(a) : "l"(p));
    return a;
}
__device__ __forceinline__ void cp16(uint32_t s, const void* g) {
    asm volatile("cp.async.cg.shared.global [%0], [%1], 16;" :: "r"(s), "l"(g));
}
__device__ __forceinline__ void ldsm4(uint32_t& r0, uint32_t& r1, uint32_t& r2,
                                      uint32_t& r3, uint32_t a) {
    asm volatile("ldmatrix.sync.aligned.m8n8.x4.shared.b16 {%0,%1,%2,%3}, [%4];"
                 : "=r"(r0), "=r"(r1), "=r"(r2), "=r"(r3) : "r"(a));
}
__device__ __forceinline__ void ldsm4t(uint32_t& r0, uint32_t& r1, uint32_t& r2,
                                       uint32_t& r3, uint32_t a) {
    asm volatile("ldmatrix.sync.aligned.m8n8.x4.trans.shared.b16 {%0,%1,%2,%3}, [%4];"
                 : "=r"(r0), "=r"(r1), "=r"(r2), "=r"(r3) : "r"(a));
}
__device__ __forceinline__ void mma16816(float* d, const uint32_t* a,
                                         uint32_t b0, uint32_t b1) {
    asm volatile("mma.sync.aligned.m16n8k16.row.col.f32.f16.f16.f32 "
                 "{%0,%1,%2,%3}, {%4,%5,%6,%7}, {%8,%9}, {%0,%1,%2,%3};"
                 : "+f"(d[0]), "+f"(d[1]), "+f"(d[2]), "+f"(d[3])
                 : "r"(a[0]), "r"(a[1]), "r"(a[2]), "r"(a[3]), "r"(b0), "r"(b1));
}

// ---- mbarrier primitives (baseline sm_90 PTX, no 'a' features) ----
__device__ __forceinline__ void mbar_init(uint32_t a, uint32_t cnt) {
    asm volatile("mbarrier.init.shared.b64 [%0], %1;" :: "r"(a), "r"(cnt) : "memory");
}
__device__ __forceinline__ void mbar_arrive(uint32_t a) {
    uint64_t st;
    asm volatile("mbarrier.arrive.shared.b64 %0, [%1];" : "=l"(st) : "r"(a) : "memory");
}
// NOTE .noinc: consume one of the pre-initialized arrival counts.
// (non-noinc form increments pending count first -> barrier never flips -> R11 hang)
__device__ __forceinline__ void cp_arrive(uint32_t a) {
    asm volatile("cp.async.mbarrier.arrive.noinc.shared.b64 [%0];" :: "r"(a) : "memory");
}
__device__ __forceinline__ void mbar_wait(uint32_t a, uint32_t p) {
    uint32_t done;
    asm volatile("{\n.reg .pred P;\n"
                 "mbarrier.try_wait.parity.shared.b64 P, [%1], %2;\n"
                 "selp.b32 %0,1,0,P;\n}"
                 : "=r"(done) : "r"(a), "r"(p) : "memory");
    while (!done) {
        asm volatile("{\n.reg .pred P;\n"
                     "mbarrier.try_wait.parity.shared.b64 P, [%1], %2, 0x989680;\n"
                     "selp.b32 %0,1,0,P;\n}"
                     : "=r"(done) : "r"(a), "r"(p) : "memory");
    }
}

// ---------------------------------------------------------------------------
// 1) x fp32 -> fp16
// ---------------------------------------------------------------------------
__global__ void convert_x_kernel(const float* __restrict__ x) {
    size_t i = ((size_t)blockIdx.x * blockDim.x + threadIdx.x) * 4;
    float4 v = *reinterpret_cast<const float4*>(x + i);
    __half2* p = reinterpret_cast<__half2*>(g_A + i);
    p[0] = __floats2half2_rn(v.x, v.y);
    p[1] = __floats2half2_rn(v.z, v.w);
}

// ---------------------------------------------------------------------------
// 2) dequant int4 -> fp16 W [K, N]
// ---------------------------------------------------------------------------
__global__ void dequant_kernel(const int* __restrict__ qw,
                               const int* __restrict__ qz,
                               const float* __restrict__ sc) {
    int idx = blockIdx.x * blockDim.x + threadIdx.x;   // 4096 * 1376 threads
    int k  = idx / (NN / 8);
    int n8 = idx - k * (NN / 8);
    int n0 = n8 * 8;
    int g  = k >> 7;
    unsigned zw = (unsigned)qz[g * (NN / 8) + n8];
    int shift = (k & 7) * 4;
    const int*   qrow = qw + (size_t)(k >> 3) * NN + n0;
    const float* srow = sc + (size_t)g * NN + n0;
    union { __half h[8]; uint4 v; } r;
#pragma unroll
    for (int j = 0; j < 8; j++) {
        int q = ((unsigned)qrow[j] >> shift) & 0xF;
        int z = (int)((zw >> (4 * j)) & 0xFu) + 1;
        r.h[j] = __float2half_rn((float)(q - z) * srow[j]);
    }
    *reinterpret_cast<uint4*>(g_W + (size_t)k * NN + n0) = r.v;
}

// ---------------------------------------------------------------------------
// 3) HMMA GEMM: out[M,N] = A[M,K] * W[K,N] + bias
//    BM=128 BN=128 BK=64, 3-stage, 96KB -> 2 CTAs/SM, 8 warps 2m x 4n,
//    mbarrier producer/consumer pacing (no __syncthreads rendezvous)
// ---------------------------------------------------------------------------
#define BM 128
#define BN 128
#define BK 64
#define STAGES 3
#define A_BYTES (BM * BK * 2)              // 16 KB, 128 rows x 128B
#define B_BYTES (BK * BN * 2)              // 16 KB, 64 rows x 256B
#define STAGE_BYTES (A_BYTES + B_BYTES)    // 32 KB
#define SMEM_BYTES (STAGES * STAGE_BYTES)  // 96 KB -> 2 CTAs/SM
#define KITERS (KK / BK)                   // 64

#define SWZA(r, c) ((uint32_t)((r) * 128 + ((((c) ^ ((r) & 7))) << 4)))
#define SWZB(r, c) ((uint32_t)((r) * 256 + ((((c) ^ ((r) & 7))) << 4)))

__global__ void __launch_bounds__(256, 2)
gemm_kernel(const float* __restrict__ bias, float* __restrict__ out) {
    extern __shared__ char smem[];
    __shared__ uint64_t bars[2 * STAGES];          // full[0..2], empty[0..2]
    const uint32_t sb = smem_u32(smem);
    const uint32_t fb = smem_u32(bars);            // full[s] = fb+8s, empty[s] = fb+24+8s
    const int tid = threadIdx.x;
    const int wid = tid >> 5;
    const int lane = tid & 31;
    const int m0 = blockIdx.x * BM;        // 32 m-tiles (fast: share W in L2)
    const int n0 = blockIdx.y * BN;        // 86 n-tiles
    const int wm = wid & 1;                // 0..1 (64 rows)
    const int wn = wid >> 1;               // 0..3 (32 cols)

    if (tid == 0) {
#pragma unroll
        for (int s = 0; s < STAGES; s++) {
            mbar_init(fb + 8 * s, 256);            // full: 256 cp-noinc arrivals
            mbar_init(fb + 24 + 8 * s, 256);       // empty: 256 thread arrivals
        }
    }
    __syncthreads();                                // inits visible; only barrier

    // rolling global load pointers (advance one chunk per produce)
    const char* aLoad = (const char*)(g_A + (size_t)m0 * KK);
    const char* bLoad = (const char*)(g_W + n0);

    auto produce = [&](int s) {
        uint32_t sA = sb + s * STAGE_BYTES;
        uint32_t sB = sA + A_BYTES;
#pragma unroll
        for (int j = 0; j < 4; j++) {      // A: 1024 x 16B (128 rows x 128B)
            int q = j * 256 + tid;
            int r = q >> 3, c = q & 7;
            cp16(sA + SWZA(r, c), aLoad + (size_t)r * (KK * 2) + c * 16);
        }
#pragma unroll
        for (int j = 0; j < 4; j++) {      // B: 1024 x 16B (64 rows x 256B)
            int q = j * 256 + tid;
            int r = q >> 4, c = q & 15;
            cp16(sB + SWZB(r, c), bLoad + (size_t)r * (NN * 2) + c * 16);
        }
        aLoad += BK * 2;
        bLoad += (size_t)BK * NN * 2;
        cp_arrive(fb + 8 * s);             // arrive(noinc) full[s] on completion
    };

    // precomputed LDSM addresses (validated in R10)
    const int x  = lane & 7;
    const int h  = lane >> 4;
    const int xk = x >> 1;
    const int xb = (x & 1) ^ h;
    uint32_t aBase[4];
#pragma unroll
    for (int mi = 0; mi < 4; mi++)
        aBase[mi] = (uint32_t)((wm * 64 + mi * 16 + (lane & 15)) * 128 + 16 * xb);
    uint32_t kso[4];
#pragma unroll
    for (int ks = 0; ks < 4; ks++) kso[ks] = (uint32_t)(32 * (ks ^ xk));
    uint32_t bBase[2];
#pragma unroll
    for (int nb = 0; nb < 2; nb++) {
        int c = wn * 4 + nb * 2 + h;
        bBase[nb] = (uint32_t)((lane & 15) * 256 + ((c ^ x) << 4));
    }

    // prologue: fill stages 0,1 (buffers empty; no wait needed)
    produce(0);
    produce(1);

    float acc[4][4][4];
#pragma unroll
    for (int i = 0; i < 4; i++)
#pragma unroll
        for (int j = 0; j < 4; j++)
#pragma unroll
            for (int e = 0; e < 4; e++) acc[i][j][e] = 0.f;

    for (int it = 0; it < KITERS; it++) {
        const int s = it % 3;
        const int r = it / 3;
        mbar_wait(fb + 8 * s, (uint32_t)(r & 1));   // stage data ready

        const uint32_t sA = sb + s * STAGE_BYTES;
        const uint32_t sB = sA + A_BYTES;
#pragma unroll
        for (int ks = 0; ks < 4; ks++) {
            uint32_t a[4][4];
#pragma unroll
            for (int mi = 0; mi < 4; mi++)
                ldsm4(a[mi][0], a[mi][1], a[mi][2], a[mi][3],
                      sA + aBase[mi] + kso[ks]);
            uint32_t b[2][4];
#pragma unroll
            for (int nb = 0; nb < 2; nb++)
                ldsm4t(b[nb][0], b[nb][1], b[nb][2], b[nb][3],
                       sB + (uint32_t)(ks * 4096) + bBase[nb]);
#pragma unroll
            for (int mi = 0; mi < 4; mi++)
#pragma unroll
                for (int ni = 0; ni < 4; ni++)
                    mma16816(acc[mi][ni], a[mi],
                             b[ni >> 1][(ni & 1) * 2], b[ni >> 1][(ni & 1) * 2 + 1]);
        }

        mbar_arrive(fb + 24 + 8 * s);               // done reading stage s

        const int j = it + 2;                        // produce chunk it+2
        if (j < KITERS) {
            const int s2 = j % 3;
            const int rj = j / 3;
            if (rj >= 1)                             // wait consumers of round rj-1
                mbar_wait(fb + 24 + 8 * s2, (uint32_t)((rj - 1) & 1));
            produce(s2);
        }
    }

    // epilogue
#pragma unroll
    for (int mi = 0; mi < 4; mi++) {
        int rr = m0 + wm * 64 + mi * 16 + (lane >> 2);
#pragma unroll
        for (int ni = 0; ni < 4; ni++) {
            int col = n0 + wn * 32 + ni * 8 + 2 * (lane & 3);
            float b0 = bias[col], b1 = bias[col + 1];
            float2 v0 = make_float2(acc[mi][ni][0] + b0, acc[mi][ni][1] + b1);
            float2 v1 = make_float2(acc[mi][ni][2] + b0, acc[mi][ni][3] + b1);
            *reinterpret_cast<float2*>(out + (size_t)rr * NN + col) = v0;
            *reinterpret_cast<float2*>(out + (size_t)(rr + 8) * NN + col) = v1;
        }
    }
}

// ---------------------------------------------------------------------------
// launch
// ---------------------------------------------------------------------------
extern "C" void kernel_launch(void* const* d_in, const int* in_sizes, int n_in,
                              void* d_out, int out_size) {
    const float* x    = (const float*)d_in[0];
    const int*   qw   = (const int*)d_in[1];
    const int*   qz   = (const int*)d_in[2];
    const float* sc   = (const float*)d_in[3];
    // d_in[4] = g_idx (k/128 by construction; unused)
    const float* bias = (const float*)d_in[5];
    float* out = (float*)d_out;

    cudaFuncSetAttribute(gemm_kernel, cudaFuncAttributeMaxDynamicSharedMemorySize,
                         SMEM_BYTES);

    convert_x_kernel<<<16384, 256>>>(x);            // 16.78M elems / 4 per thread
    dequant_kernel<<<22016, 256>>>(qw, qz, sc);     // 4096 * 1376 threads
    gemm_kernel<<<dim3(MM / BM, NN / BN), 256, SMEM_BYTES>>>(bias, out);
}